// round 6
// baseline (speedup 1.0000x reference)
#include <cuda_runtime.h>

// ---------------------------------------------------------------------------
// LSTM forecaster: 2-layer encoder (T=20, F=10, H=128) -> 2-layer decoder
// (T_FUT=30, autoregressive on 2-dim head output). Batch rows independent ->
// each CTA owns 32 rows and runs the whole recurrence locally.
//
// Thread map: 512 threads = 128 hidden-j  x  4 row-groups (8 rows each).
// Thread (j, rg) computes gates i/f/g/o for hidden unit j across its 8 rows.
// Cell state c lives in registers; h lives in smem (broadcast reads).
//
// Round 5: weight staging is software-pipelined with cp.async.cg into a
// TRIPLE-buffered smem ring (KC=16 columns per chunk). Each chunk: stage
// next chunk, cp.async.wait_group 1, ONE __syncthreads, compute. The last
// chunk of each matrix prefetches chunk 0 of the next matrix in the fixed
// 150-matrix schedule, so L2 traffic fully overlaps compute.
// ---------------------------------------------------------------------------

#define THREADS 512
#define HID     128
#define NG      4
#define GATES   512      // 4*HID
#define ROWS    32       // batch rows per CTA
#define RPT     8        // rows per thread
#define KC      16       // staged K-chunk columns
#define NCHUNK  (HID / KC)       // 8 chunks per matrix
#define WPAD    20       // smem row stride for staged weights (floats)
#define NBUF    3        // staging ring depth
#define HSTR    132      // smem row stride for h (floats)
#define XPAD    13       // smem row stride for x / Wih0 (floats)
#define T_HIST  20
#define T_FUT   30
#define FIN     10

// smem: ring 3*512*20 + Wih0 512*13 + dWih0 512*3 + biases 4*512 + head 260
//       + h0/h1 2*32*132 + x 32*13 + y 64
#define SMEM_FLOATS (NBUF*GATES*WPAD + GATES*XPAD + GATES*3 + 4*GATES + 260 \
                     + 2*ROWS*HSTR + ROWS*XPAD + 64)
#define SMEM_BYTES  (SMEM_FLOATS * 4)

__device__ __forceinline__ void fma2(unsigned long long &acc,
                                     unsigned long long a,
                                     unsigned long long b) {
    asm("fma.rn.f32x2 %0, %1, %2, %0;" : "+l"(acc) : "l"(a), "l"(b));
}
__device__ __forceinline__ unsigned long long pack2(float lo, float hi) {
    unsigned long long v;
    asm("mov.b64 %0, {%1, %2};" : "=l"(v)
        : "r"(__float_as_uint(lo)), "r"(__float_as_uint(hi)));
    return v;
}
__device__ __forceinline__ float sum2(unsigned long long v) {
    unsigned int l, h;
    asm("mov.b64 {%0, %1}, %2;" : "=r"(l), "=r"(h) : "l"(v));
    return __uint_as_float(l) + __uint_as_float(h);
}
__device__ __forceinline__ float sigf(float x) {
    return __fdividef(1.0f, 1.0f + __expf(-x));
}
__device__ __forceinline__ float tanhf_fast(float x) {
    return 1.0f - __fdividef(2.0f, __expf(2.0f * x) + 1.0f);
}

__device__ __forceinline__ unsigned int smem_u32(const void* p) {
    unsigned int a;
    asm("{ .reg .u64 t; cvta.to.shared.u64 t, %1; cvt.u32.u64 %0, t; }"
        : "=r"(a) : "l"(p));
    return a;
}
__device__ __forceinline__ void cp_async16(unsigned int dst, const void* src) {
    asm volatile("cp.async.cg.shared.global [%0], [%1], 16;"
                 :: "r"(dst), "l"(src) : "memory");
}
__device__ __forceinline__ void cp_commit() {
    asm volatile("cp.async.commit_group;" ::: "memory");
}
__device__ __forceinline__ void cp_wait1() {
    asm volatile("cp.async.wait_group 1;" ::: "memory");
}

__global__ void __launch_bounds__(THREADS, 1)
lstm_forecaster_kernel(const float* __restrict__ hist,
                       const float* __restrict__ eWih0, const float* __restrict__ eWhh0,
                       const float* __restrict__ ebih0, const float* __restrict__ ebhh0,
                       const float* __restrict__ eWih1, const float* __restrict__ eWhh1,
                       const float* __restrict__ ebih1, const float* __restrict__ ebhh1,
                       const float* __restrict__ dWih0, const float* __restrict__ dWhh0,
                       const float* __restrict__ dbih0, const float* __restrict__ dbhh0,
                       const float* __restrict__ dWih1, const float* __restrict__ dWhh1,
                       const float* __restrict__ dbih1, const float* __restrict__ dbhh1,
                       const float* __restrict__ headW, const float* __restrict__ headb,
                       float* __restrict__ out)
{
    extern __shared__ float sm[];
    float* Wring    = sm;                           // 3 * 512*20
    float* Wih0_sm  = Wring    + NBUF*GATES*WPAD;   // 512*13
    float* dWih0_sm = Wih0_sm  + GATES*XPAD;        // 512*3
    float* b_e0     = dWih0_sm + GATES*3;           // 512
    float* b_e1     = b_e0 + GATES;
    float* b_d0     = b_e1 + GATES;
    float* b_d1     = b_d0 + GATES;
    float* headW_sm = b_d1 + GATES;                 // 256
    float* headb_sm = headW_sm + 256;               // 4
    float* h0_sm    = headb_sm + 4;                 // 32*132
    float* h1_sm    = h0_sm + ROWS*HSTR;            // 32*132
    float* x_sm     = h1_sm + ROWS*HSTR;            // 32*13
    float* y_sm     = x_sm + ROWS*XPAD;             // 64

    const int tid = threadIdx.x;
    const int j   = tid & (HID - 1);
    const int rg  = tid >> 7;
    const int r0  = rg * RPT;
    const int brow = blockIdx.x * ROWS;

    // per-thread staging coords: thread handles rows (tid>>2)+{0,128,256,384},
    // 16-byte segment (tid&3)*4 within the 16-float chunk row.
    const int srow = tid >> 2;
    const int skk  = (tid & 3) << 2;
    unsigned int ring_u32 = smem_u32(Wring);

    // stage chunk (k0) of matrix W into ring slot `slot` (4 x cp.async.16B)
    auto stage = [&](const float* __restrict__ W, int k0, int slot) {
        unsigned int base = ring_u32 + (unsigned)(slot * GATES * WPAD) * 4u;
#pragma unroll
        for (int i = 0; i < 4; ++i) {
            int r = srow + i * 128;
            cp_async16(base + (unsigned)(r * WPAD + skk) * 4u,
                       W + r * HID + k0 + skk);
        }
        cp_commit();
    };

    // ---- persistent preload ----
    for (int i = tid; i < GATES * FIN; i += THREADS) {
        int row = i / FIN, f = i - row * FIN;
        Wih0_sm[row * XPAD + f] = eWih0[i];
    }
    for (int i = tid; i < GATES * 2; i += THREADS) {
        int row = i >> 1, d = i & 1;
        dWih0_sm[row * 3 + d] = dWih0[i];
    }
    {
        int i = tid;  // THREADS == GATES
        b_e0[i] = ebih0[i] + ebhh0[i];
        b_e1[i] = ebih1[i] + ebhh1[i];
        b_d0[i] = dbih0[i] + dbhh0[i];
        b_d1[i] = dbih1[i] + dbhh1[i];
    }
    if (tid < 256) headW_sm[tid] = headW[tid];
    if (tid < 2)   headb_sm[tid] = headb[tid];
    for (int i = tid; i < ROWS * HSTR; i += THREADS) { h0_sm[i] = 0.0f; h1_sm[i] = 0.0f; }
    if (tid < ROWS * 2) y_sm[tid] = 0.0f;

    // pipeline prologue: chunk 0 of the first matrix into slot 0
    stage(eWhh0, 0, 0);
    int slot = 0;   // slot holding the chunk we will compute next
    __syncthreads();

    float c0[RPT], c1[RPT];
#pragma unroll
    for (int r = 0; r < RPT; ++r) { c0[r] = 0.0f; c1[r] = 0.0f; }

    unsigned long long acc2[NG][RPT];

    // process one (512 x 128) matrix in 8 pipelined chunks; prefetch chunk 0
    // of Wnext during the last chunk.
    auto run_matrix = [&](const float* __restrict__ Wg,
                          const float* __restrict__ Wnext,
                          const float* __restrict__ hsm) {
#pragma unroll 1
        for (int c = 0; c < NCHUNK; ++c) {
            // stage the NEXT chunk into the next ring slot
            int nslot = slot + 1; if (nslot == NBUF) nslot = 0;
            if (c + 1 < NCHUNK) stage(Wg, (c + 1) * KC, nslot);
            else                stage(Wnext, 0, nslot);
            cp_wait1();          // our chunk `c` copies have landed
            __syncthreads();     // everyone's copies visible; reuse-safe (depth 3)

            const float* Wb = Wring + slot * GATES * WPAD;
            const int k0 = c * KC;
#pragma unroll
            for (int kk = 0; kk < KC; kk += 4) {
                ulonglong2 w[NG];
#pragma unroll
                for (int g = 0; g < NG; ++g)
                    w[g] = *(const ulonglong2*)(Wb + (g * HID + j) * WPAD + kk);
#pragma unroll
                for (int r = 0; r < RPT; ++r) {
                    ulonglong2 hd = *(const ulonglong2*)(hsm + (r0 + r) * HSTR + k0 + kk);
#pragma unroll
                    for (int g = 0; g < NG; ++g) {
                        fma2(acc2[g][r], w[g].x, hd.x);
                        fma2(acc2[g][r], w[g].y, hd.y);
                    }
                }
            }
            slot = nslot;
        }
    };

    auto init_bias = [&](const float* __restrict__ bsm) {
#pragma unroll
        for (int g = 0; g < NG; ++g) {
            float bg = bsm[g * HID + j];
#pragma unroll
            for (int r = 0; r < RPT; ++r) acc2[g][r] = pack2(bg, 0.0f);
        }
    };

    auto finish_layer = [&](float (&c)[RPT], float* __restrict__ hsm_out) {
        float hn[RPT];
#pragma unroll
        for (int r = 0; r < RPT; ++r) {
            float gi = sigf(sum2(acc2[0][r]));
            float gf = sigf(sum2(acc2[1][r]));
            float gg = tanhf_fast(sum2(acc2[2][r]));
            float go = sigf(sum2(acc2[3][r]));
            float cn = gf * c[r] + gi * gg;
            c[r] = cn;
            hn[r] = go * tanhf_fast(cn);
        }
        __syncthreads();   // all reads of old h done before overwrite
#pragma unroll
        for (int r = 0; r < RPT; ++r) hsm_out[(r0 + r) * HSTR + j] = hn[r];
    };

    // ================= encoder =================
#pragma unroll 1
    for (int t = 0; t < T_HIST; ++t) {
        if (tid < ROWS * FIN) {
            int r = tid / FIN, f = tid - r * FIN;
            x_sm[r * XPAD + f] =
                hist[(size_t)(brow + r) * (T_HIST * FIN) + t * FIN + f];
        }
        __syncthreads();

        // --- layer 0: bias + x-part in fp32, then pack ---
        {
            float a[NG][RPT];
#pragma unroll
            for (int g = 0; g < NG; ++g) {
                float bg = b_e0[g * HID + j];
#pragma unroll
                for (int r = 0; r < RPT; ++r) a[g][r] = bg;
            }
#pragma unroll
            for (int f = 0; f < FIN; ++f) {
                float wg[NG];
#pragma unroll
                for (int g = 0; g < NG; ++g)
                    wg[g] = Wih0_sm[(g * HID + j) * XPAD + f];
#pragma unroll
                for (int r = 0; r < RPT; ++r) {
                    float xv = x_sm[(r0 + r) * XPAD + f];
#pragma unroll
                    for (int g = 0; g < NG; ++g) a[g][r] += wg[g] * xv;
                }
            }
#pragma unroll
            for (int g = 0; g < NG; ++g)
#pragma unroll
                for (int r = 0; r < RPT; ++r) acc2[g][r] = pack2(a[g][r], 0.0f);
        }
        run_matrix(eWhh0, eWih1, h0_sm);
        finish_layer(c0, h0_sm);

        // --- layer 1 ---
        init_bias(b_e1);
        run_matrix(eWih1, eWhh1, h0_sm);                       // input = new h0
        run_matrix(eWhh1, (t + 1 < T_HIST) ? eWhh0 : dWhh0, h1_sm);
        finish_layer(c1, h1_sm);
    }

    // ================= decoder =================
#pragma unroll 1
    for (int t = 0; t < T_FUT; ++t) {
        // --- layer 0: bias + y-part (2 dims) ---
        {
            float a[NG][RPT];
#pragma unroll
            for (int g = 0; g < NG; ++g) {
                float bg = b_d0[g * HID + j];
#pragma unroll
                for (int r = 0; r < RPT; ++r) a[g][r] = bg;
            }
#pragma unroll
            for (int d = 0; d < 2; ++d) {
                float wg[NG];
#pragma unroll
                for (int g = 0; g < NG; ++g)
                    wg[g] = dWih0_sm[(g * HID + j) * 3 + d];
#pragma unroll
                for (int r = 0; r < RPT; ++r) {
                    float yv = y_sm[(r0 + r) * 2 + d];
#pragma unroll
                    for (int g = 0; g < NG; ++g) a[g][r] += wg[g] * yv;
                }
            }
#pragma unroll
            for (int g = 0; g < NG; ++g)
#pragma unroll
                for (int r = 0; r < RPT; ++r) acc2[g][r] = pack2(a[g][r], 0.0f);
        }
        run_matrix(dWhh0, dWih1, h0_sm);
        finish_layer(c0, h0_sm);

        // --- layer 1 ---
        init_bias(b_d1);
        run_matrix(dWih1, dWhh1, h0_sm);
        run_matrix(dWhh1, (t + 1 < T_FUT) ? dWhh0 : eWhh0, h1_sm);
        finish_layer(c1, h1_sm);
        __syncthreads();   // h1 stores visible before head reads

        // --- head: dxy = h1 @ headW^T + headb ---
        if (tid < ROWS * 2) {
            int r = tid >> 1, d = tid & 1;
            float s = headb_sm[d];
            const float* hw = headW_sm + d * HID;
            const float* hr = h1_sm + r * HSTR;
#pragma unroll 8
            for (int jj = 0; jj < HID; ++jj) s += hr[jj] * hw[jj];
            y_sm[r * 2 + d] = s;
            out[(size_t)(brow + r) * (T_FUT * 2) + t * 2 + d] = s;
        }
        __syncthreads();   // y_sm visible before next step's y-part
    }
}

extern "C" void kernel_launch(void* const* d_in, const int* in_sizes, int n_in,
                              void* d_out, int out_size)
{
    const float* hist  = (const float*)d_in[0];
    const float* eWih0 = (const float*)d_in[1];
    const float* eWhh0 = (const float*)d_in[2];
    const float* ebih0 = (const float*)d_in[3];
    const float* ebhh0 = (const float*)d_in[4];
    const float* eWih1 = (const float*)d_in[5];
    const float* eWhh1 = (const float*)d_in[6];
    const float* ebih1 = (const float*)d_in[7];
    const float* ebhh1 = (const float*)d_in[8];
    const float* dWih0 = (const float*)d_in[9];
    const float* dWhh0 = (const float*)d_in[10];
    const float* dbih0 = (const float*)d_in[11];
    const float* dbhh0 = (const float*)d_in[12];
    const float* dWih1 = (const float*)d_in[13];
    const float* dWhh1 = (const float*)d_in[14];
    const float* dbih1 = (const float*)d_in[15];
    const float* dbhh1 = (const float*)d_in[16];
    const float* headW = (const float*)d_in[17];
    const float* headb = (const float*)d_in[18];
    // d_in[19] = fut_len (always 30 for this problem)

    int B = in_sizes[0] / (T_HIST * FIN);
    int grid = B / ROWS;

    cudaFuncSetAttribute(lstm_forecaster_kernel,
                         cudaFuncAttributeMaxDynamicSharedMemorySize, SMEM_BYTES);

    lstm_forecaster_kernel<<<grid, THREADS, SMEM_BYTES>>>(
        hist, eWih0, eWhh0, ebih0, ebhh0, eWih1, eWhh1, ebih1, ebhh1,
        dWih0, dWhh0, dbih0, dbhh0, dWih1, dWhh1, dbih1, dbhh1,
        headW, headb, (float*)d_out);
}

// round 8
// speedup vs baseline: 1.0002x; 1.0002x over previous
#include <cuda_runtime.h>

// ---------------------------------------------------------------------------
// LSTM forecaster: 2-layer encoder (T=20, F=10, H=128) -> 2-layer decoder
// (T_FUT=30, autoregressive on 2-dim head output). Batch rows independent ->
// each CTA owns 32 rows and runs the whole recurrence locally.
//
// Thread map: 512 threads = 128 hidden-j  x  4 row-groups (8 rows each).
// Thread (j, rg) computes gates i/f/g/o for hidden unit j across its 8 rows.
// Cell state c lives in registers; h lives in smem (broadcast reads).
//
// Round 5: weight staging is software-pipelined with cp.async.cg into a
// TRIPLE-buffered smem ring (KC=16 columns per chunk). Each chunk: stage
// next chunk, cp.async.wait_group 1, ONE __syncthreads, compute. The last
// chunk of each matrix prefetches chunk 0 of the next matrix in the fixed
// 150-matrix schedule, so L2 traffic fully overlaps compute.
// ---------------------------------------------------------------------------

#define THREADS 512
#define HID     128
#define NG      4
#define GATES   512      // 4*HID
#define ROWS    32       // batch rows per CTA
#define RPT     8        // rows per thread
#define KC      16       // staged K-chunk columns
#define NCHUNK  (HID / KC)       // 8 chunks per matrix
#define WPAD    20       // smem row stride for staged weights (floats)
#define NBUF    3        // staging ring depth
#define HSTR    132      // smem row stride for h (floats)
#define XPAD    13       // smem row stride for x / Wih0 (floats)
#define T_HIST  20
#define T_FUT   30
#define FIN     10

// smem: ring 3*512*20 + Wih0 512*13 + dWih0 512*3 + biases 4*512 + head 260
//       + h0/h1 2*32*132 + x 32*13 + y 64
#define SMEM_FLOATS (NBUF*GATES*WPAD + GATES*XPAD + GATES*3 + 4*GATES + 260 \
                     + 2*ROWS*HSTR + ROWS*XPAD + 64)
#define SMEM_BYTES  (SMEM_FLOATS * 4)

__device__ __forceinline__ void fma2(unsigned long long &acc,
                                     unsigned long long a,
                                     unsigned long long b) {
    asm("fma.rn.f32x2 %0, %1, %2, %0;" : "+l"(acc) : "l"(a), "l"(b));
}
__device__ __forceinline__ unsigned long long pack2(float lo, float hi) {
    unsigned long long v;
    asm("mov.b64 %0, {%1, %2};" : "=l"(v)
        : "r"(__float_as_uint(lo)), "r"(__float_as_uint(hi)));
    return v;
}
__device__ __forceinline__ float sum2(unsigned long long v) {
    unsigned int l, h;
    asm("mov.b64 {%0, %1}, %2;" : "=r"(l), "=r"(h) : "l"(v));
    return __uint_as_float(l) + __uint_as_float(h);
}
__device__ __forceinline__ float sigf(float x) {
    return __fdividef(1.0f, 1.0f + __expf(-x));
}
__device__ __forceinline__ float tanhf_fast(float x) {
    return 1.0f - __fdividef(2.0f, __expf(2.0f * x) + 1.0f);
}

__device__ __forceinline__ unsigned int smem_u32(const void* p) {
    unsigned int a;
    asm("{ .reg .u64 t; cvta.to.shared.u64 t, %1; cvt.u32.u64 %0, t; }"
        : "=r"(a) : "l"(p));
    return a;
}
__device__ __forceinline__ void cp_async16(unsigned int dst, const void* src) {
    asm volatile("cp.async.cg.shared.global [%0], [%1], 16;"
                 :: "r"(dst), "l"(src) : "memory");
}
__device__ __forceinline__ void cp_commit() {
    asm volatile("cp.async.commit_group;" ::: "memory");
}
__device__ __forceinline__ void cp_wait1() {
    asm volatile("cp.async.wait_group 1;" ::: "memory");
}

__global__ void __launch_bounds__(THREADS, 1)
lstm_forecaster_kernel(const float* __restrict__ hist,
                       const float* __restrict__ eWih0, const float* __restrict__ eWhh0,
                       const float* __restrict__ ebih0, const float* __restrict__ ebhh0,
                       const float* __restrict__ eWih1, const float* __restrict__ eWhh1,
                       const float* __restrict__ ebih1, const float* __restrict__ ebhh1,
                       const float* __restrict__ dWih0, const float* __restrict__ dWhh0,
                       const float* __restrict__ dbih0, const float* __restrict__ dbhh0,
                       const float* __restrict__ dWih1, const float* __restrict__ dWhh1,
                       const float* __restrict__ dbih1, const float* __restrict__ dbhh1,
                       const float* __restrict__ headW, const float* __restrict__ headb,
                       float* __restrict__ out)
{
    extern __shared__ float sm[];
    float* Wring    = sm;                           // 3 * 512*20
    float* Wih0_sm  = Wring    + NBUF*GATES*WPAD;   // 512*13
    float* dWih0_sm = Wih0_sm  + GATES*XPAD;        // 512*3
    float* b_e0     = dWih0_sm + GATES*3;           // 512
    float* b_e1     = b_e0 + GATES;
    float* b_d0     = b_e1 + GATES;
    float* b_d1     = b_d0 + GATES;
    float* headW_sm = b_d1 + GATES;                 // 256
    float* headb_sm = headW_sm + 256;               // 4
    float* h0_sm    = headb_sm + 4;                 // 32*132
    float* h1_sm    = h0_sm + ROWS*HSTR;            // 32*132
    float* x_sm     = h1_sm + ROWS*HSTR;            // 32*13
    float* y_sm     = x_sm + ROWS*XPAD;             // 64

    const int tid = threadIdx.x;
    const int j   = tid & (HID - 1);
    const int rg  = tid >> 7;
    const int r0  = rg * RPT;
    const int brow = blockIdx.x * ROWS;

    // per-thread staging coords: thread handles rows (tid>>2)+{0,128,256,384},
    // 16-byte segment (tid&3)*4 within the 16-float chunk row.
    const int srow = tid >> 2;
    const int skk  = (tid & 3) << 2;
    unsigned int ring_u32 = smem_u32(Wring);

    // stage chunk (k0) of matrix W into ring slot `slot` (4 x cp.async.16B)
    auto stage = [&](const float* __restrict__ W, int k0, int slot) {
        unsigned int base = ring_u32 + (unsigned)(slot * GATES * WPAD) * 4u;
#pragma unroll
        for (int i = 0; i < 4; ++i) {
            int r = srow + i * 128;
            cp_async16(base + (unsigned)(r * WPAD + skk) * 4u,
                       W + r * HID + k0 + skk);
        }
        cp_commit();
    };

    // ---- persistent preload ----
    for (int i = tid; i < GATES * FIN; i += THREADS) {
        int row = i / FIN, f = i - row * FIN;
        Wih0_sm[row * XPAD + f] = eWih0[i];
    }
    for (int i = tid; i < GATES * 2; i += THREADS) {
        int row = i >> 1, d = i & 1;
        dWih0_sm[row * 3 + d] = dWih0[i];
    }
    {
        int i = tid;  // THREADS == GATES
        b_e0[i] = ebih0[i] + ebhh0[i];
        b_e1[i] = ebih1[i] + ebhh1[i];
        b_d0[i] = dbih0[i] + dbhh0[i];
        b_d1[i] = dbih1[i] + dbhh1[i];
    }
    if (tid < 256) headW_sm[tid] = headW[tid];
    if (tid < 2)   headb_sm[tid] = headb[tid];
    for (int i = tid; i < ROWS * HSTR; i += THREADS) { h0_sm[i] = 0.0f; h1_sm[i] = 0.0f; }
    if (tid < ROWS * 2) y_sm[tid] = 0.0f;

    // pipeline prologue: chunk 0 of the first matrix into slot 0
    stage(eWhh0, 0, 0);
    int slot = 0;   // slot holding the chunk we will compute next
    __syncthreads();

    float c0[RPT], c1[RPT];
#pragma unroll
    for (int r = 0; r < RPT; ++r) { c0[r] = 0.0f; c1[r] = 0.0f; }

    unsigned long long acc2[NG][RPT];

    // process one (512 x 128) matrix in 8 pipelined chunks; prefetch chunk 0
    // of Wnext during the last chunk.
    auto run_matrix = [&](const float* __restrict__ Wg,
                          const float* __restrict__ Wnext,
                          const float* __restrict__ hsm) {
#pragma unroll 1
        for (int c = 0; c < NCHUNK; ++c) {
            // stage the NEXT chunk into the next ring slot
            int nslot = slot + 1; if (nslot == NBUF) nslot = 0;
            if (c + 1 < NCHUNK) stage(Wg, (c + 1) * KC, nslot);
            else                stage(Wnext, 0, nslot);
            cp_wait1();          // our chunk `c` copies have landed
            __syncthreads();     // everyone's copies visible; reuse-safe (depth 3)

            const float* Wb = Wring + slot * GATES * WPAD;
            const int k0 = c * KC;
#pragma unroll
            for (int kk = 0; kk < KC; kk += 4) {
                ulonglong2 w[NG];
#pragma unroll
                for (int g = 0; g < NG; ++g)
                    w[g] = *(const ulonglong2*)(Wb + (g * HID + j) * WPAD + kk);
#pragma unroll
                for (int r = 0; r < RPT; ++r) {
                    ulonglong2 hd = *(const ulonglong2*)(hsm + (r0 + r) * HSTR + k0 + kk);
#pragma unroll
                    for (int g = 0; g < NG; ++g) {
                        fma2(acc2[g][r], w[g].x, hd.x);
                        fma2(acc2[g][r], w[g].y, hd.y);
                    }
                }
            }
            slot = nslot;
        }
    };

    auto init_bias = [&](const float* __restrict__ bsm) {
#pragma unroll
        for (int g = 0; g < NG; ++g) {
            float bg = bsm[g * HID + j];
#pragma unroll
            for (int r = 0; r < RPT; ++r) acc2[g][r] = pack2(bg, 0.0f);
        }
    };

    auto finish_layer = [&](float (&c)[RPT], float* __restrict__ hsm_out) {
        float hn[RPT];
#pragma unroll
        for (int r = 0; r < RPT; ++r) {
            float gi = sigf(sum2(acc2[0][r]));
            float gf = sigf(sum2(acc2[1][r]));
            float gg = tanhf_fast(sum2(acc2[2][r]));
            float go = sigf(sum2(acc2[3][r]));
            float cn = gf * c[r] + gi * gg;
            c[r] = cn;
            hn[r] = go * tanhf_fast(cn);
        }
        __syncthreads();   // all reads of old h done before overwrite
#pragma unroll
        for (int r = 0; r < RPT; ++r) hsm_out[(r0 + r) * HSTR + j] = hn[r];
    };

    // ================= encoder =================
#pragma unroll 1
    for (int t = 0; t < T_HIST; ++t) {
        if (tid < ROWS * FIN) {
            int r = tid / FIN, f = tid - r * FIN;
            x_sm[r * XPAD + f] =
                hist[(size_t)(brow + r) * (T_HIST * FIN) + t * FIN + f];
        }
        __syncthreads();

        // --- layer 0: bias + x-part in fp32, then pack ---
        {
            float a[NG][RPT];
#pragma unroll
            for (int g = 0; g < NG; ++g) {
                float bg = b_e0[g * HID + j];
#pragma unroll
                for (int r = 0; r < RPT; ++r) a[g][r] = bg;
            }
#pragma unroll
            for (int f = 0; f < FIN; ++f) {
                float wg[NG];
#pragma unroll
                for (int g = 0; g < NG; ++g)
                    wg[g] = Wih0_sm[(g * HID + j) * XPAD + f];
#pragma unroll
                for (int r = 0; r < RPT; ++r) {
                    float xv = x_sm[(r0 + r) * XPAD + f];
#pragma unroll
                    for (int g = 0; g < NG; ++g) a[g][r] += wg[g] * xv;
                }
            }
#pragma unroll
            for (int g = 0; g < NG; ++g)
#pragma unroll
                for (int r = 0; r < RPT; ++r) acc2[g][r] = pack2(a[g][r], 0.0f);
        }
        run_matrix(eWhh0, eWih1, h0_sm);
        finish_layer(c0, h0_sm);

        // --- layer 1 ---
        init_bias(b_e1);
        run_matrix(eWih1, eWhh1, h0_sm);                       // input = new h0
        run_matrix(eWhh1, (t + 1 < T_HIST) ? eWhh0 : dWhh0, h1_sm);
        finish_layer(c1, h1_sm);
    }

    // ================= decoder =================
#pragma unroll 1
    for (int t = 0; t < T_FUT; ++t) {
        // --- layer 0: bias + y-part (2 dims) ---
        {
            float a[NG][RPT];
#pragma unroll
            for (int g = 0; g < NG; ++g) {
                float bg = b_d0[g * HID + j];
#pragma unroll
                for (int r = 0; r < RPT; ++r) a[g][r] = bg;
            }
#pragma unroll
            for (int d = 0; d < 2; ++d) {
                float wg[NG];
#pragma unroll
                for (int g = 0; g < NG; ++g)
                    wg[g] = dWih0_sm[(g * HID + j) * 3 + d];
#pragma unroll
                for (int r = 0; r < RPT; ++r) {
                    float yv = y_sm[(r0 + r) * 2 + d];
#pragma unroll
                    for (int g = 0; g < NG; ++g) a[g][r] += wg[g] * yv;
                }
            }
#pragma unroll
            for (int g = 0; g < NG; ++g)
#pragma unroll
                for (int r = 0; r < RPT; ++r) acc2[g][r] = pack2(a[g][r], 0.0f);
        }
        run_matrix(dWhh0, dWih1, h0_sm);
        finish_layer(c0, h0_sm);

        // --- layer 1 ---
        init_bias(b_d1);
        run_matrix(dWih1, dWhh1, h0_sm);
        run_matrix(dWhh1, (t + 1 < T_FUT) ? dWhh0 : eWhh0, h1_sm);
        finish_layer(c1, h1_sm);
        __syncthreads();   // h1 stores visible before head reads

        // --- head: dxy = h1 @ headW^T + headb ---
        if (tid < ROWS * 2) {
            int r = tid >> 1, d = tid & 1;
            float s = headb_sm[d];
            const float* hw = headW_sm + d * HID;
            const float* hr = h1_sm + r * HSTR;
#pragma unroll 8
            for (int jj = 0; jj < HID; ++jj) s += hr[jj] * hw[jj];
            y_sm[r * 2 + d] = s;
            out[(size_t)(brow + r) * (T_FUT * 2) + t * 2 + d] = s;
        }
        __syncthreads();   // y_sm visible before next step's y-part
    }
}

extern "C" void kernel_launch(void* const* d_in, const int* in_sizes, int n_in,
                              void* d_out, int out_size)
{
    const float* hist  = (const float*)d_in[0];
    const float* eWih0 = (const float*)d_in[1];
    const float* eWhh0 = (const float*)d_in[2];
    const float* ebih0 = (const float*)d_in[3];
    const float* ebhh0 = (const float*)d_in[4];
    const float* eWih1 = (const float*)d_in[5];
    const float* eWhh1 = (const float*)d_in[6];
    const float* ebih1 = (const float*)d_in[7];
    const float* ebhh1 = (const float*)d_in[8];
    const float* dWih0 = (const float*)d_in[9];
    const float* dWhh0 = (const float*)d_in[10];
    const float* dbih0 = (const float*)d_in[11];
    const float* dbhh0 = (const float*)d_in[12];
    const float* dWih1 = (const float*)d_in[13];
    const float* dWhh1 = (const float*)d_in[14];
    const float* dbih1 = (const float*)d_in[15];
    const float* dbhh1 = (const float*)d_in[16];
    const float* headW = (const float*)d_in[17];
    const float* headb = (const float*)d_in[18];
    // d_in[19] = fut_len (always 30 for this problem)

    int B = in_sizes[0] / (T_HIST * FIN);
    int grid = B / ROWS;

    cudaFuncSetAttribute(lstm_forecaster_kernel,
                         cudaFuncAttributeMaxDynamicSharedMemorySize, SMEM_BYTES);

    lstm_forecaster_kernel<<<grid, THREADS, SMEM_BYTES>>>(
        hist, eWih0, eWhh0, ebih0, ebhh0, eWih1, eWhh1, ebih1, ebhh1,
        dWih0, dWhh0, dbih0, dbhh0, dWih1, dWhh1, dbih1, dbhh1,
        headW, headb, (float*)d_out);
}

// round 9
// speedup vs baseline: 1.0005x; 1.0003x over previous
#include <cuda_runtime.h>

// ---------------------------------------------------------------------------
// LSTM forecaster: 2-layer encoder (T=20, F=10, H=128) -> 2-layer decoder
// (T_FUT=30, autoregressive on 2-dim head output). Batch rows independent ->
// each CTA owns 32 rows and runs the whole recurrence locally.
//
// Thread map: 512 threads = 128 hidden-j  x  4 row-groups (8 rows each).
// Thread (j, rg) computes gates i/f/g/o for hidden unit j across its 8 rows.
// Cell state c lives in registers; h lives in smem (broadcast reads).
//
// Round 5: weight staging is software-pipelined with cp.async.cg into a
// TRIPLE-buffered smem ring (KC=16 columns per chunk). Each chunk: stage
// next chunk, cp.async.wait_group 1, ONE __syncthreads, compute. The last
// chunk of each matrix prefetches chunk 0 of the next matrix in the fixed
// 150-matrix schedule, so L2 traffic fully overlaps compute.
// ---------------------------------------------------------------------------

#define THREADS 512
#define HID     128
#define NG      4
#define GATES   512      // 4*HID
#define ROWS    32       // batch rows per CTA
#define RPT     8        // rows per thread
#define KC      16       // staged K-chunk columns
#define NCHUNK  (HID / KC)       // 8 chunks per matrix
#define WPAD    20       // smem row stride for staged weights (floats)
#define NBUF    3        // staging ring depth
#define HSTR    132      // smem row stride for h (floats)
#define XPAD    13       // smem row stride for x / Wih0 (floats)
#define T_HIST  20
#define T_FUT   30
#define FIN     10

// smem: ring 3*512*20 + Wih0 512*13 + dWih0 512*3 + biases 4*512 + head 260
//       + h0/h1 2*32*132 + x 32*13 + y 64
#define SMEM_FLOATS (NBUF*GATES*WPAD + GATES*XPAD + GATES*3 + 4*GATES + 260 \
                     + 2*ROWS*HSTR + ROWS*XPAD + 64)
#define SMEM_BYTES  (SMEM_FLOATS * 4)

__device__ __forceinline__ void fma2(unsigned long long &acc,
                                     unsigned long long a,
                                     unsigned long long b) {
    asm("fma.rn.f32x2 %0, %1, %2, %0;" : "+l"(acc) : "l"(a), "l"(b));
}
__device__ __forceinline__ unsigned long long pack2(float lo, float hi) {
    unsigned long long v;
    asm("mov.b64 %0, {%1, %2};" : "=l"(v)
        : "r"(__float_as_uint(lo)), "r"(__float_as_uint(hi)));
    return v;
}
__device__ __forceinline__ float sum2(unsigned long long v) {
    unsigned int l, h;
    asm("mov.b64 {%0, %1}, %2;" : "=r"(l), "=r"(h) : "l"(v));
    return __uint_as_float(l) + __uint_as_float(h);
}
__device__ __forceinline__ float sigf(float x) {
    return __fdividef(1.0f, 1.0f + __expf(-x));
}
__device__ __forceinline__ float tanhf_fast(float x) {
    return 1.0f - __fdividef(2.0f, __expf(2.0f * x) + 1.0f);
}

__device__ __forceinline__ unsigned int smem_u32(const void* p) {
    unsigned int a;
    asm("{ .reg .u64 t; cvta.to.shared.u64 t, %1; cvt.u32.u64 %0, t; }"
        : "=r"(a) : "l"(p));
    return a;
}
__device__ __forceinline__ void cp_async16(unsigned int dst, const void* src) {
    asm volatile("cp.async.cg.shared.global [%0], [%1], 16;"
                 :: "r"(dst), "l"(src) : "memory");
}
__device__ __forceinline__ void cp_commit() {
    asm volatile("cp.async.commit_group;" ::: "memory");
}
__device__ __forceinline__ void cp_wait1() {
    asm volatile("cp.async.wait_group 1;" ::: "memory");
}

__global__ void __launch_bounds__(THREADS, 1)
lstm_forecaster_kernel(const float* __restrict__ hist,
                       const float* __restrict__ eWih0, const float* __restrict__ eWhh0,
                       const float* __restrict__ ebih0, const float* __restrict__ ebhh0,
                       const float* __restrict__ eWih1, const float* __restrict__ eWhh1,
                       const float* __restrict__ ebih1, const float* __restrict__ ebhh1,
                       const float* __restrict__ dWih0, const float* __restrict__ dWhh0,
                       const float* __restrict__ dbih0, const float* __restrict__ dbhh0,
                       const float* __restrict__ dWih1, const float* __restrict__ dWhh1,
                       const float* __restrict__ dbih1, const float* __restrict__ dbhh1,
                       const float* __restrict__ headW, const float* __restrict__ headb,
                       float* __restrict__ out)
{
    extern __shared__ float sm[];
    float* Wring    = sm;                           // 3 * 512*20
    float* Wih0_sm  = Wring    + NBUF*GATES*WPAD;   // 512*13
    float* dWih0_sm = Wih0_sm  + GATES*XPAD;        // 512*3
    float* b_e0     = dWih0_sm + GATES*3;           // 512
    float* b_e1     = b_e0 + GATES;
    float* b_d0     = b_e1 + GATES;
    float* b_d1     = b_d0 + GATES;
    float* headW_sm = b_d1 + GATES;                 // 256
    float* headb_sm = headW_sm + 256;               // 4
    float* h0_sm    = headb_sm + 4;                 // 32*132
    float* h1_sm    = h0_sm + ROWS*HSTR;            // 32*132
    float* x_sm     = h1_sm + ROWS*HSTR;            // 32*13
    float* y_sm     = x_sm + ROWS*XPAD;             // 64

    const int tid = threadIdx.x;
    const int j   = tid & (HID - 1);
    const int rg  = tid >> 7;
    const int r0  = rg * RPT;
    const int brow = blockIdx.x * ROWS;

    // per-thread staging coords: thread handles rows (tid>>2)+{0,128,256,384},
    // 16-byte segment (tid&3)*4 within the 16-float chunk row.
    const int srow = tid >> 2;
    const int skk  = (tid & 3) << 2;
    unsigned int ring_u32 = smem_u32(Wring);

    // stage chunk (k0) of matrix W into ring slot `slot` (4 x cp.async.16B)
    auto stage = [&](const float* __restrict__ W, int k0, int slot) {
        unsigned int base = ring_u32 + (unsigned)(slot * GATES * WPAD) * 4u;
#pragma unroll
        for (int i = 0; i < 4; ++i) {
            int r = srow + i * 128;
            cp_async16(base + (unsigned)(r * WPAD + skk) * 4u,
                       W + r * HID + k0 + skk);
        }
        cp_commit();
    };

    // ---- persistent preload ----
    for (int i = tid; i < GATES * FIN; i += THREADS) {
        int row = i / FIN, f = i - row * FIN;
        Wih0_sm[row * XPAD + f] = eWih0[i];
    }
    for (int i = tid; i < GATES * 2; i += THREADS) {
        int row = i >> 1, d = i & 1;
        dWih0_sm[row * 3 + d] = dWih0[i];
    }
    {
        int i = tid;  // THREADS == GATES
        b_e0[i] = ebih0[i] + ebhh0[i];
        b_e1[i] = ebih1[i] + ebhh1[i];
        b_d0[i] = dbih0[i] + dbhh0[i];
        b_d1[i] = dbih1[i] + dbhh1[i];
    }
    if (tid < 256) headW_sm[tid] = headW[tid];
    if (tid < 2)   headb_sm[tid] = headb[tid];
    for (int i = tid; i < ROWS * HSTR; i += THREADS) { h0_sm[i] = 0.0f; h1_sm[i] = 0.0f; }
    if (tid < ROWS * 2) y_sm[tid] = 0.0f;

    // pipeline prologue: chunk 0 of the first matrix into slot 0
    stage(eWhh0, 0, 0);
    int slot = 0;   // slot holding the chunk we will compute next
    __syncthreads();

    float c0[RPT], c1[RPT];
#pragma unroll
    for (int r = 0; r < RPT; ++r) { c0[r] = 0.0f; c1[r] = 0.0f; }

    unsigned long long acc2[NG][RPT];

    // process one (512 x 128) matrix in 8 pipelined chunks; prefetch chunk 0
    // of Wnext during the last chunk.
    auto run_matrix = [&](const float* __restrict__ Wg,
                          const float* __restrict__ Wnext,
                          const float* __restrict__ hsm) {
#pragma unroll 1
        for (int c = 0; c < NCHUNK; ++c) {
            // stage the NEXT chunk into the next ring slot
            int nslot = slot + 1; if (nslot == NBUF) nslot = 0;
            if (c + 1 < NCHUNK) stage(Wg, (c + 1) * KC, nslot);
            else                stage(Wnext, 0, nslot);
            cp_wait1();          // our chunk `c` copies have landed
            __syncthreads();     // everyone's copies visible; reuse-safe (depth 3)

            const float* Wb = Wring + slot * GATES * WPAD;
            const int k0 = c * KC;
#pragma unroll
            for (int kk = 0; kk < KC; kk += 4) {
                ulonglong2 w[NG];
#pragma unroll
                for (int g = 0; g < NG; ++g)
                    w[g] = *(const ulonglong2*)(Wb + (g * HID + j) * WPAD + kk);
#pragma unroll
                for (int r = 0; r < RPT; ++r) {
                    ulonglong2 hd = *(const ulonglong2*)(hsm + (r0 + r) * HSTR + k0 + kk);
#pragma unroll
                    for (int g = 0; g < NG; ++g) {
                        fma2(acc2[g][r], w[g].x, hd.x);
                        fma2(acc2[g][r], w[g].y, hd.y);
                    }
                }
            }
            slot = nslot;
        }
    };

    auto init_bias = [&](const float* __restrict__ bsm) {
#pragma unroll
        for (int g = 0; g < NG; ++g) {
            float bg = bsm[g * HID + j];
#pragma unroll
            for (int r = 0; r < RPT; ++r) acc2[g][r] = pack2(bg, 0.0f);
        }
    };

    auto finish_layer = [&](float (&c)[RPT], float* __restrict__ hsm_out) {
        float hn[RPT];
#pragma unroll
        for (int r = 0; r < RPT; ++r) {
            float gi = sigf(sum2(acc2[0][r]));
            float gf = sigf(sum2(acc2[1][r]));
            float gg = tanhf_fast(sum2(acc2[2][r]));
            float go = sigf(sum2(acc2[3][r]));
            float cn = gf * c[r] + gi * gg;
            c[r] = cn;
            hn[r] = go * tanhf_fast(cn);
        }
        __syncthreads();   // all reads of old h done before overwrite
#pragma unroll
        for (int r = 0; r < RPT; ++r) hsm_out[(r0 + r) * HSTR + j] = hn[r];
    };

    // ================= encoder =================
#pragma unroll 1
    for (int t = 0; t < T_HIST; ++t) {
        if (tid < ROWS * FIN) {
            int r = tid / FIN, f = tid - r * FIN;
            x_sm[r * XPAD + f] =
                hist[(size_t)(brow + r) * (T_HIST * FIN) + t * FIN + f];
        }
        __syncthreads();

        // --- layer 0: bias + x-part in fp32, then pack ---
        {
            float a[NG][RPT];
#pragma unroll
            for (int g = 0; g < NG; ++g) {
                float bg = b_e0[g * HID + j];
#pragma unroll
                for (int r = 0; r < RPT; ++r) a[g][r] = bg;
            }
#pragma unroll
            for (int f = 0; f < FIN; ++f) {
                float wg[NG];
#pragma unroll
                for (int g = 0; g < NG; ++g)
                    wg[g] = Wih0_sm[(g * HID + j) * XPAD + f];
#pragma unroll
                for (int r = 0; r < RPT; ++r) {
                    float xv = x_sm[(r0 + r) * XPAD + f];
#pragma unroll
                    for (int g = 0; g < NG; ++g) a[g][r] += wg[g] * xv;
                }
            }
#pragma unroll
            for (int g = 0; g < NG; ++g)
#pragma unroll
                for (int r = 0; r < RPT; ++r) acc2[g][r] = pack2(a[g][r], 0.0f);
        }
        run_matrix(eWhh0, eWih1, h0_sm);
        finish_layer(c0, h0_sm);

        // --- layer 1 ---
        init_bias(b_e1);
        run_matrix(eWih1, eWhh1, h0_sm);                       // input = new h0
        run_matrix(eWhh1, (t + 1 < T_HIST) ? eWhh0 : dWhh0, h1_sm);
        finish_layer(c1, h1_sm);
    }

    // ================= decoder =================
#pragma unroll 1
    for (int t = 0; t < T_FUT; ++t) {
        // --- layer 0: bias + y-part (2 dims) ---
        {
            float a[NG][RPT];
#pragma unroll
            for (int g = 0; g < NG; ++g) {
                float bg = b_d0[g * HID + j];
#pragma unroll
                for (int r = 0; r < RPT; ++r) a[g][r] = bg;
            }
#pragma unroll
            for (int d = 0; d < 2; ++d) {
                float wg[NG];
#pragma unroll
                for (int g = 0; g < NG; ++g)
                    wg[g] = dWih0_sm[(g * HID + j) * 3 + d];
#pragma unroll
                for (int r = 0; r < RPT; ++r) {
                    float yv = y_sm[(r0 + r) * 2 + d];
#pragma unroll
                    for (int g = 0; g < NG; ++g) a[g][r] += wg[g] * yv;
                }
            }
#pragma unroll
            for (int g = 0; g < NG; ++g)
#pragma unroll
                for (int r = 0; r < RPT; ++r) acc2[g][r] = pack2(a[g][r], 0.0f);
        }
        run_matrix(dWhh0, dWih1, h0_sm);
        finish_layer(c0, h0_sm);

        // --- layer 1 ---
        init_bias(b_d1);
        run_matrix(dWih1, dWhh1, h0_sm);
        run_matrix(dWhh1, (t + 1 < T_FUT) ? dWhh0 : eWhh0, h1_sm);
        finish_layer(c1, h1_sm);
        __syncthreads();   // h1 stores visible before head reads

        // --- head: dxy = h1 @ headW^T + headb ---
        if (tid < ROWS * 2) {
            int r = tid >> 1, d = tid & 1;
            float s = headb_sm[d];
            const float* hw = headW_sm + d * HID;
            const float* hr = h1_sm + r * HSTR;
#pragma unroll 8
            for (int jj = 0; jj < HID; ++jj) s += hr[jj] * hw[jj];
            y_sm[r * 2 + d] = s;
            out[(size_t)(brow + r) * (T_FUT * 2) + t * 2 + d] = s;
        }
        __syncthreads();   // y_sm visible before next step's y-part
    }
}

extern "C" void kernel_launch(void* const* d_in, const int* in_sizes, int n_in,
                              void* d_out, int out_size)
{
    const float* hist  = (const float*)d_in[0];
    const float* eWih0 = (const float*)d_in[1];
    const float* eWhh0 = (const float*)d_in[2];
    const float* ebih0 = (const float*)d_in[3];
    const float* ebhh0 = (const float*)d_in[4];
    const float* eWih1 = (const float*)d_in[5];
    const float* eWhh1 = (const float*)d_in[6];
    const float* ebih1 = (const float*)d_in[7];
    const float* ebhh1 = (const float*)d_in[8];
    const float* dWih0 = (const float*)d_in[9];
    const float* dWhh0 = (const float*)d_in[10];
    const float* dbih0 = (const float*)d_in[11];
    const float* dbhh0 = (const float*)d_in[12];
    const float* dWih1 = (const float*)d_in[13];
    const float* dWhh1 = (const float*)d_in[14];
    const float* dbih1 = (const float*)d_in[15];
    const float* dbhh1 = (const float*)d_in[16];
    const float* headW = (const float*)d_in[17];
    const float* headb = (const float*)d_in[18];
    // d_in[19] = fut_len (always 30 for this problem)

    int B = in_sizes[0] / (T_HIST * FIN);
    int grid = B / ROWS;

    cudaFuncSetAttribute(lstm_forecaster_kernel,
                         cudaFuncAttributeMaxDynamicSharedMemorySize, SMEM_BYTES);

    lstm_forecaster_kernel<<<grid, THREADS, SMEM_BYTES>>>(
        hist, eWih0, eWhh0, ebih0, ebhh0, eWih1, eWhh1, ebih1, ebhh1,
        dWih0, dWhh0, dbih0, dbhh0, dWih1, dWhh1, dbih1, dbhh1,
        headW, headb, (float*)d_out);
}

// round 10
// speedup vs baseline: 4.7687x; 4.7665x over previous
#include <cuda_runtime.h>
#include <cuda_fp16.h>

// ---------------------------------------------------------------------------
// LSTM forecaster via fp16 tensor-core MMA (mma.sync.m16n8k16, fp32 accum).
//
// Per CTA: 64 batch rows, whole 50-step recurrence local.
// A (smem, fp16): hcat rows = [h0(128) | x/y(16) | h1(128) | pad], stride 296.
// B (smem, fp16): weight chunk (512 gates x 16 k), staged by cp.async double
//   buffer from pre-built fp16 weight images in __device__ global memory:
//     encL0: [eWhh0 | eWih0 pad]        K=144
//     encL1: [eWih1 | 0(16) | eWhh1]    K=272
//     decL0: [dWhh0 | dWih0 pad]        K=144
//     decL1: [dWih1 | 0(16) | dWhh1]    K=272
// Warp w owns gate columns {g*128 + 8w .. +8} for g=0..3 -> after MMA each
// thread holds i,f,g,o of its cells in registers; elementwise finish is
// register-local; c-state fp32 in smem; h written back fp16 into hcat.
// ---------------------------------------------------------------------------

#define THREADS 512
#define HID     128
#define GATES   512
#define ROWS    64
#define HS      296      // hcat stride (halves)
#define CS      132      // c-state stride (floats)
#define WSTR    24       // weight-chunk smem row stride (halves); 16 data + 8 pad
#define WBUFB   (512*WSTR*2)   // bytes per weight buffer = 24576
#define T_HIST  20
#define T_FUT   30
#define FIN     10

// weight image geometry (halves)
#define K_L0    144
#define K_L1    272
#define NK_L0   9
#define NK_L1   17
#define SZ_L0   (512*K_L0)     // 73728
#define SZ_L1   (512*K_L1)     // 139264
#define OFF_E0  0
#define OFF_E1  (SZ_L0)
#define OFF_D0  (SZ_L0 + SZ_L1)
#define OFF_D1  (2*SZ_L0 + SZ_L1)
#define WIMG_TOTAL (2*SZ_L0 + 2*SZ_L1)   // 425984

// smem layout (bytes)
#define WBUF_OFF  0
#define HCAT_OFF  (2*WBUFB)                     // 49152
#define CST0_OFF  (HCAT_OFF + ROWS*HS*2)        // 49152+37888 = 87040
#define CST1_OFF  (CST0_OFF + ROWS*CS*4)        // +33792 = 120832
#define BIAS_OFF  (CST1_OFF + ROWS*CS*4)        // +33792 = 154624
#define HEADW_OFF (BIAS_OFF + 4*GATES*4)        // +8192 = 162816
#define HEADB_OFF (HEADW_OFF + 1024)            // 163840
#define SMEM_BYTES (HEADB_OFF + 32)             // 163872

__device__ __align__(16) __half g_wimg[WIMG_TOTAL];

// ---------------- device helpers ----------------
__device__ __forceinline__ float sigf(float x) {
    return __fdividef(1.0f, 1.0f + __expf(-x));
}
__device__ __forceinline__ float tanhf_fast(float x) {
    return 1.0f - __fdividef(2.0f, __expf(2.0f * x) + 1.0f);
}
__device__ __forceinline__ unsigned int smem_u32(const void* p) {
    unsigned int a;
    asm("{ .reg .u64 t; cvta.to.shared.u64 t, %1; cvt.u32.u64 %0, t; }"
        : "=r"(a) : "l"(p));
    return a;
}
__device__ __forceinline__ void cp_async16(unsigned int dst, const void* src) {
    asm volatile("cp.async.cg.shared.global [%0], [%1], 16;"
                 :: "r"(dst), "l"(src) : "memory");
}
__device__ __forceinline__ void cp_commit() {
    asm volatile("cp.async.commit_group;" ::: "memory");
}
__device__ __forceinline__ void cp_wait1() {
    asm volatile("cp.async.wait_group 1;" ::: "memory");
}
__device__ __forceinline__ void cp_wait0() {
    asm volatile("cp.async.wait_group 0;" ::: "memory");
}
__device__ __forceinline__ void ldsm_x4(unsigned int* r, unsigned int addr) {
    asm volatile("ldmatrix.sync.aligned.m8n8.x4.shared.b16 {%0,%1,%2,%3}, [%4];"
                 : "=r"(r[0]), "=r"(r[1]), "=r"(r[2]), "=r"(r[3]) : "r"(addr));
}
__device__ __forceinline__ void ldsm_x2(unsigned int& r0, unsigned int& r1,
                                        unsigned int addr) {
    asm volatile("ldmatrix.sync.aligned.m8n8.x2.shared.b16 {%0,%1}, [%2];"
                 : "=r"(r0), "=r"(r1) : "r"(addr));
}
__device__ __forceinline__ void mma16816(float* d, const unsigned int* a,
                                         unsigned int b0, unsigned int b1) {
    asm volatile(
        "mma.sync.aligned.m16n8k16.row.col.f32.f16.f16.f32 "
        "{%0,%1,%2,%3},{%4,%5,%6,%7},{%8,%9},{%0,%1,%2,%3};"
        : "+f"(d[0]), "+f"(d[1]), "+f"(d[2]), "+f"(d[3])
        : "r"(a[0]), "r"(a[1]), "r"(a[2]), "r"(a[3]), "r"(b0), "r"(b1));
}

// ---------------- prep kernel: fp32 weights -> fp16 concat images ----------
__global__ void prep_weights(const float* __restrict__ eWih0, const float* __restrict__ eWhh0,
                             const float* __restrict__ eWih1, const float* __restrict__ eWhh1,
                             const float* __restrict__ dWih0, const float* __restrict__ dWhh0,
                             const float* __restrict__ dWih1, const float* __restrict__ dWhh1)
{
    int idx = blockIdx.x * blockDim.x + threadIdx.x;
    if (idx >= WIMG_TOTAL) return;
    float v = 0.0f;
    if (idx < OFF_E1) {                       // encL0 [eWhh0 | eWih0 | 0]
        int i = idx, g = i / K_L0, k = i - g * K_L0;
        if (k < 128)       v = eWhh0[g * 128 + k];
        else if (k < 138)  v = eWih0[g * FIN + (k - 128)];
    } else if (idx < OFF_D0) {                // encL1 [eWih1 | 0 | eWhh1]
        int i = idx - OFF_E1, g = i / K_L1, k = i - g * K_L1;
        if (k < 128)       v = eWih1[g * 128 + k];
        else if (k >= 144) v = eWhh1[g * 128 + (k - 144)];
    } else if (idx < OFF_D1) {                // decL0 [dWhh0 | dWih0 | 0]
        int i = idx - OFF_D0, g = i / K_L0, k = i - g * K_L0;
        if (k < 128)       v = dWhh0[g * 128 + k];
        else if (k < 130)  v = dWih0[g * 2 + (k - 128)];
    } else {                                  // decL1 [dWih1 | 0 | dWhh1]
        int i = idx - OFF_D1, g = i / K_L1, k = i - g * K_L1;
        if (k < 128)       v = dWih1[g * 128 + k];
        else if (k >= 144) v = dWhh1[g * 128 + (k - 144)];
    }
    g_wimg[idx] = __float2half(v);
}

// ---------------- main kernel ----------------
__global__ void __launch_bounds__(THREADS, 1)
lstm_mma_kernel(const float* __restrict__ hist,
                const float* __restrict__ ebih0, const float* __restrict__ ebhh0,
                const float* __restrict__ ebih1, const float* __restrict__ ebhh1,
                const float* __restrict__ dbih0, const float* __restrict__ dbhh0,
                const float* __restrict__ dbih1, const float* __restrict__ dbhh1,
                const float* __restrict__ headW, const float* __restrict__ headb,
                float* __restrict__ out)
{
    extern __shared__ char smraw[];
    __half* wbuf  = (__half*)(smraw + WBUF_OFF);
    __half* hcat  = (__half*)(smraw + HCAT_OFF);
    float*  cst0  = (float*)(smraw + CST0_OFF);
    float*  cst1  = (float*)(smraw + CST1_OFF);
    float*  bias  = (float*)(smraw + BIAS_OFF);   // 4 x 512
    float*  headWs= (float*)(smraw + HEADW_OFF);  // 256
    float*  headbs= (float*)(smraw + HEADB_OFF);  // 2

    const int tid  = threadIdx.x;
    const int lane = tid & 31;
    const int warp = tid >> 5;
    const int tg   = lane >> 2;       // 0..7
    const int tp   = lane & 3;        // 0..3
    const int j0   = warp * 8;        // hidden-j base for this warp
    const int brow = blockIdx.x * ROWS;

    const unsigned int wbuf_u32 = smem_u32(wbuf);
    const unsigned int hcat_u32 = smem_u32(hcat);

    // ldmatrix address precomputation
    const int arow = (lane & 7) + (((lane >> 3) & 1) << 3);     // A row in 16-row tile
    const unsigned int aoff = (unsigned)((arow * HS + ((lane >> 4) & 1) * 8) * 2);
    const int l2 = lane & 15;
    unsigned int boffg[4];
#pragma unroll
    for (int g = 0; g < 4; ++g)
        boffg[g] = (unsigned)(((g * 128 + j0 + (l2 & 7)) * WSTR + ((l2 >> 3) & 1) * 8) * 2);

    // ---- prologue: zero state, load biases/head ----
    for (int i = tid; i < ROWS * HS; i += THREADS) hcat[i] = __float2half(0.0f);
    for (int i = tid; i < ROWS * CS; i += THREADS) { cst0[i] = 0.0f; cst1[i] = 0.0f; }
    {
        int i = tid;  // THREADS == GATES
        bias[i]        = ebih0[i] + ebhh0[i];
        bias[512 + i]  = ebih1[i] + ebhh1[i];
        bias[1024 + i] = dbih0[i] + dbhh0[i];
        bias[1536 + i] = dbih1[i] + dbhh1[i];
    }
    if (tid < 256) headWs[tid] = headW[tid];
    if (tid < 2)   headbs[tid] = headb[tid];
    __syncthreads();

    int sbuf = 0, cbuf = 0;

    auto stage = [&](const __half* img, int Kimg, int s) {
        int row = tid >> 1;
        int seg = (tid & 1) * 8;
        unsigned int base = wbuf_u32 + (unsigned)(sbuf * WBUFB);
        cp_async16(base + (unsigned)((row * WSTR + seg) * 2),
                   img + row * Kimg + s * 16 + seg);
        row += 256;
        cp_async16(base + (unsigned)((row * WSTR + seg) * 2),
                   img + row * Kimg + s * 16 + seg);
        cp_commit();
        sbuf ^= 1;
    };

    float acc[4][4][4];   // [mtile][gate][creg]

    auto init_acc = [&](const float* bs) {
        const int jc = j0 + 2 * tp;
#pragma unroll
        for (int g = 0; g < 4; ++g) {
            float b0 = bs[g * 128 + jc];
            float b1 = bs[g * 128 + jc + 1];
#pragma unroll
            for (int m = 0; m < 4; ++m) {
                acc[m][g][0] = b0; acc[m][g][1] = b1;
                acc[m][g][2] = b0; acc[m][g][3] = b1;
            }
        }
    };

    auto run_matrix = [&](const __half* img, int Kimg, int nk,
                          const __half* nimg, int nKimg) {
#pragma unroll 1
        for (int s = 0; s < nk; ++s) {
            if (s + 1 < nk) stage(img, Kimg, s + 1);
            else            stage(nimg, nKimg, 0);
            cp_wait1();
            __syncthreads();
            const unsigned int wb = wbuf_u32 + (unsigned)(cbuf * WBUFB);
            cbuf ^= 1;
            unsigned int a[4][4];
#pragma unroll
            for (int m = 0; m < 4; ++m)
                ldsm_x4(a[m], hcat_u32 + aoff + (unsigned)((m * 16 * HS + s * 16) * 2));
#pragma unroll
            for (int g = 0; g < 4; ++g) {
                unsigned int b0, b1;
                ldsm_x2(b0, b1, wb + boffg[g]);
#pragma unroll
                for (int m = 0; m < 4; ++m)
                    mma16816(acc[m][g], a[m], b0, b1);
            }
        }
        __syncthreads();   // all MMA reads of hcat done before h overwrite
    };

    auto finish = [&](float* cs, int outcol) {
#pragma unroll
        for (int m = 0; m < 4; ++m) {
#pragma unroll
            for (int rr = 0; rr < 2; ++rr) {
                const int row = m * 16 + tg + rr * 8;
                const int jc  = j0 + 2 * tp;
                float hv[2];
#pragma unroll
                for (int cc = 0; cc < 2; ++cc) {
                    const int ci = rr * 2 + cc;
                    float gi = sigf(acc[m][0][ci]);
                    float gf = sigf(acc[m][1][ci]);
                    float gg = tanhf_fast(acc[m][2][ci]);
                    float go = sigf(acc[m][3][ci]);
                    float cold = cs[row * CS + jc + cc];
                    float cn = gf * cold + gi * gg;
                    cs[row * CS + jc + cc] = cn;
                    hv[cc] = go * tanhf_fast(cn);
                }
                *(__half2*)(hcat + row * HS + outcol + jc) =
                    __floats2half2_rn(hv[0], hv[1]);
            }
        }
    };

    const __half* IMG_E0 = g_wimg + OFF_E0;
    const __half* IMG_E1 = g_wimg + OFF_E1;
    const __half* IMG_D0 = g_wimg + OFF_D0;
    const __half* IMG_D1 = g_wimg + OFF_D1;

    // pipeline prologue: chunk 0 of first matrix
    stage(IMG_E0, K_L0, 0);

    // ================= encoder =================
#pragma unroll 1
    for (int t = 0; t < T_HIST; ++t) {
        // write x(t) into hcat cols 128..137 (fp16); cols 138..143 stay 0
        for (int i = tid; i < ROWS * FIN; i += THREADS) {
            int r = i / FIN, f = i - r * FIN;
            hcat[r * HS + 128 + f] =
                __float2half(hist[(size_t)(brow + r) * (T_HIST * FIN) + t * FIN + f]);
        }
        init_acc(bias);
        run_matrix(IMG_E0, K_L0, NK_L0, IMG_E1, K_L1);
        finish(cst0, 0);

        init_acc(bias + 512);
        run_matrix(IMG_E1, K_L1, NK_L1, (t + 1 < T_HIST) ? IMG_E0 : IMG_D0, K_L0);
        finish(cst1, 144);
    }

    // zero the x/y slot so decoder starts from y0 = 0
    for (int i = tid; i < ROWS * 16; i += THREADS) {
        int r = i >> 4, c = i & 15;
        hcat[r * HS + 128 + c] = __float2half(0.0f);
    }

    // ================= decoder =================
#pragma unroll 1
    for (int t = 0; t < T_FUT; ++t) {
        init_acc(bias + 1024);
        run_matrix(IMG_D0, K_L0, NK_L0, IMG_D1, K_L1);
        finish(cst0, 0);

        init_acc(bias + 1536);
        run_matrix(IMG_D1, K_L1, NK_L1, IMG_D0, K_L0);
        finish(cst1, 144);
        __syncthreads();   // h1 stores visible before head reads

        // head: dxy = h1 @ headW^T + headb ; write y back into hcat fp16
        if (tid < ROWS * 2) {
            int r = tid >> 1, d = tid & 1;
            float s = headbs[d];
            const __half* hr = hcat + r * HS + 144;
            const float*  hw = headWs + d * 128;
#pragma unroll 8
            for (int jj = 0; jj < HID; ++jj)
                s += __half2float(hr[jj]) * hw[jj];
            out[(size_t)(brow + r) * (T_FUT * 2) + t * 2 + d] = s;
            hcat[r * HS + 128 + d] = __float2half(s);
        }
        // next decL0's chunk barrier publishes y before it is read
    }

    cp_wait0();   // drain dangling prefetch before CTA exit (smem reuse safety)
}

extern "C" void kernel_launch(void* const* d_in, const int* in_sizes, int n_in,
                              void* d_out, int out_size)
{
    const float* hist  = (const float*)d_in[0];
    const float* eWih0 = (const float*)d_in[1];
    const float* eWhh0 = (const float*)d_in[2];
    const float* ebih0 = (const float*)d_in[3];
    const float* ebhh0 = (const float*)d_in[4];
    const float* eWih1 = (const float*)d_in[5];
    const float* eWhh1 = (const float*)d_in[6];
    const float* ebih1 = (const float*)d_in[7];
    const float* ebhh1 = (const float*)d_in[8];
    const float* dWih0 = (const float*)d_in[9];
    const float* dWhh0 = (const float*)d_in[10];
    const float* dbih0 = (const float*)d_in[11];
    const float* dbhh0 = (const float*)d_in[12];
    const float* dWih1 = (const float*)d_in[13];
    const float* dWhh1 = (const float*)d_in[14];
    const float* dbih1 = (const float*)d_in[15];
    const float* dbhh1 = (const float*)d_in[16];
    const float* headW = (const float*)d_in[17];
    const float* headb = (const float*)d_in[18];

    int B = in_sizes[0] / (T_HIST * FIN);
    int grid = B / ROWS;

    prep_weights<<<(WIMG_TOTAL + 511) / 512, 512>>>(
        eWih0, eWhh0, eWih1, eWhh1, dWih0, dWhh0, dWih1, dWhh1);

    cudaFuncSetAttribute(lstm_mma_kernel,
                         cudaFuncAttributeMaxDynamicSharedMemorySize, SMEM_BYTES);

    lstm_mma_kernel<<<grid, THREADS, SMEM_BYTES>>>(
        hist, ebih0, ebhh0, ebih1, ebhh1, dbih0, dbhh0, dbih1, dbhh1,
        headW, headb, (float*)d_out);
}

// round 15
// speedup vs baseline: 5.0904x; 1.0675x over previous
#include <cuda_runtime.h>
#include <cuda_fp16.h>

// ---------------------------------------------------------------------------
// LSTM forecaster via fp16 tensor-core MMA (mma.sync.m16n8k16, fp32 accum).
//
// Per CTA: 64 batch rows, whole 50-step recurrence local.
// A (smem, fp16): hcat rows = [h0(128) | x/y(16) | h1(128) | pad], stride 296.
// B (smem, fp16): per-warp PRIVATE weight slabs (4 gates x 8 rows x 16 k),
//   cp.async 3-deep ring, cp.async.wait_group 2, NO per-chunk __syncthreads.
//   Weight images (fp16, built by prep kernel in device global memory):
//     encL0: [eWhh0 | eWih0 pad]        K=144
//     encL1: [eWih1 | 0(16) | eWhh1]    K=272
//     decL0: [dWhh0 | dWih0 pad]        K=144
//     decL1: [dWih1 | 0(16) | dWhh1]    K=272
// Warp w owns gate columns {g*128 + 8w .. +8} for g=0..3 -> each thread holds
// i,f,g,o of its cells in registers after MMA; elementwise finish is
// register-local; c-state fp32 in smem; h written back fp16 into hcat.
// Barriers only at matrix boundaries (hcat producer/consumer handoff).
// ---------------------------------------------------------------------------

#define THREADS 512
#define HID     128
#define GATES   512
#define ROWS    64
#define HS      296      // hcat stride (halves)
#define CS      132      // c-state stride (floats)
#define T_HIST  20
#define T_FUT   30
#define FIN     10

// per-warp weight slab: 32 rows (4 gates x 8) x 48B (16 halves + 8 pad)
#define WSTRB   48
#define GSTRB   384            // 8 rows * 48B per gate block
#define SLABB   1536           // 32 * 48
#define NRING   3

// weight image geometry (halves)
#define K_L0    144
#define K_L1    272
#define NK_L0   9
#define NK_L1   17
#define SZ_L0   (512*K_L0)     // 73728
#define SZ_L1   (512*K_L1)     // 139264
#define OFF_E0  0
#define OFF_E1  (SZ_L0)
#define OFF_D0  (SZ_L0 + SZ_L1)
#define OFF_D1  (2*SZ_L0 + SZ_L1)
#define WIMG_TOTAL (2*SZ_L0 + 2*SZ_L1)   // 425984

// smem layout (bytes)
#define WBUF_OFF  0
#define WBUF_SZ   (16*NRING*SLABB)              // 73728
#define HCAT_OFF  (WBUF_OFF + WBUF_SZ)          // 73728
#define CST0_OFF  (HCAT_OFF + ROWS*HS*2)        // +37888 = 111616
#define CST1_OFF  (CST0_OFF + ROWS*CS*4)        // +33792 = 145408
#define BIAS_OFF  (CST1_OFF + ROWS*CS*4)        // +33792 = 179200
#define HEADW_OFF (BIAS_OFF + 4*GATES*4)        // +8192  = 187392
#define HEADB_OFF (HEADW_OFF + 1024)            // 188416
#define SMEM_BYTES (HEADB_OFF + 32)             // 188448

__device__ __align__(16) __half g_wimg[WIMG_TOTAL];

// ---------------- device helpers ----------------
__device__ __forceinline__ float sigf(float x) {
    return __fdividef(1.0f, 1.0f + __expf(-x));
}
__device__ __forceinline__ float tanhf_fast(float x) {
    return 1.0f - __fdividef(2.0f, __expf(2.0f * x) + 1.0f);
}
__device__ __forceinline__ unsigned int smem_u32(const void* p) {
    unsigned int a;
    asm("{ .reg .u64 t; cvta.to.shared.u64 t, %1; cvt.u32.u64 %0, t; }"
        : "=r"(a) : "l"(p));
    return a;
}
__device__ __forceinline__ void cp_async16(unsigned int dst, const void* src) {
    asm volatile("cp.async.cg.shared.global [%0], [%1], 16;"
                 :: "r"(dst), "l"(src) : "memory");
}
__device__ __forceinline__ void cp_commit() {
    asm volatile("cp.async.commit_group;" ::: "memory");
}
__device__ __forceinline__ void cp_wait2() {
    asm volatile("cp.async.wait_group 2;" ::: "memory");
}
__device__ __forceinline__ void cp_wait0() {
    asm volatile("cp.async.wait_group 0;" ::: "memory");
}
__device__ __forceinline__ void ldsm_x4(unsigned int* r, unsigned int addr) {
    asm volatile("ldmatrix.sync.aligned.m8n8.x4.shared.b16 {%0,%1,%2,%3}, [%4];"
                 : "=r"(r[0]), "=r"(r[1]), "=r"(r[2]), "=r"(r[3]) : "r"(addr));
}
__device__ __forceinline__ void ldsm_x2(unsigned int& r0, unsigned int& r1,
                                        unsigned int addr) {
    asm volatile("ldmatrix.sync.aligned.m8n8.x2.shared.b16 {%0,%1}, [%2];"
                 : "=r"(r0), "=r"(r1) : "r"(addr));
}
__device__ __forceinline__ void mma16816(float* d, const unsigned int* a,
                                         unsigned int b0, unsigned int b1) {
    asm volatile(
        "mma.sync.aligned.m16n8k16.row.col.f32.f16.f16.f32 "
        "{%0,%1,%2,%3},{%4,%5,%6,%7},{%8,%9},{%0,%1,%2,%3};"
        : "+f"(d[0]), "+f"(d[1]), "+f"(d[2]), "+f"(d[3])
        : "r"(a[0]), "r"(a[1]), "r"(a[2]), "r"(a[3]), "r"(b0), "r"(b1));
}

// ---------------- prep kernel: fp32 weights -> fp16 concat images ----------
__global__ void prep_weights(const float* __restrict__ eWih0, const float* __restrict__ eWhh0,
                             const float* __restrict__ eWih1, const float* __restrict__ eWhh1,
                             const float* __restrict__ dWih0, const float* __restrict__ dWhh0,
                             const float* __restrict__ dWih1, const float* __restrict__ dWhh1)
{
    int idx = blockIdx.x * blockDim.x + threadIdx.x;
    if (idx >= WIMG_TOTAL) return;
    float v = 0.0f;
    if (idx < OFF_E1) {                       // encL0 [eWhh0 | eWih0 | 0]
        int i = idx, g = i / K_L0, k = i - g * K_L0;
        if (k < 128)       v = eWhh0[g * 128 + k];
        else if (k < 138)  v = eWih0[g * FIN + (k - 128)];
    } else if (idx < OFF_D0) {                // encL1 [eWih1 | 0 | eWhh1]
        int i = idx - OFF_E1, g = i / K_L1, k = i - g * K_L1;
        if (k < 128)       v = eWih1[g * 128 + k];
        else if (k >= 144) v = eWhh1[g * 128 + (k - 144)];
    } else if (idx < OFF_D1) {                // decL0 [dWhh0 | dWih0 | 0]
        int i = idx - OFF_D0, g = i / K_L0, k = i - g * K_L0;
        if (k < 128)       v = dWhh0[g * 128 + k];
        else if (k < 130)  v = dWih0[g * 2 + (k - 128)];
    } else {                                  // decL1 [dWih1 | 0 | dWhh1]
        int i = idx - OFF_D1, g = i / K_L1, k = i - g * K_L1;
        if (k < 128)       v = dWih1[g * 128 + k];
        else if (k >= 144) v = dWhh1[g * 128 + (k - 144)];
    }
    g_wimg[idx] = __float2half(v);
}

// ---------------- main kernel ----------------
__global__ void __launch_bounds__(THREADS, 1)
lstm_mma_kernel(const float* __restrict__ hist,
                const float* __restrict__ ebih0, const float* __restrict__ ebhh0,
                const float* __restrict__ ebih1, const float* __restrict__ ebhh1,
                const float* __restrict__ dbih0, const float* __restrict__ dbhh0,
                const float* __restrict__ dbih1, const float* __restrict__ dbhh1,
                const float* __restrict__ headW, const float* __restrict__ headb,
                float* __restrict__ out)
{
    extern __shared__ char smraw[];
    __half* hcat  = (__half*)(smraw + HCAT_OFF);
    float*  cst0  = (float*)(smraw + CST0_OFF);
    float*  cst1  = (float*)(smraw + CST1_OFF);
    float*  bias  = (float*)(smraw + BIAS_OFF);   // 4 x 512
    float*  headWs= (float*)(smraw + HEADW_OFF);  // 256
    float*  headbs= (float*)(smraw + HEADB_OFF);  // 2

    const int tid  = threadIdx.x;
    const int lane = tid & 31;
    const int warp = tid >> 5;
    const int tg   = lane >> 2;       // 0..7
    const int tp   = lane & 3;        // 0..3
    const int j0   = warp * 8;        // hidden-j base for this warp
    const int brow = blockIdx.x * ROWS;

    const unsigned int wbase = smem_u32(smraw + WBUF_OFF)
                             + (unsigned)(warp * NRING * SLABB);
    const unsigned int hcat_u32 = smem_u32(hcat);

    // ldmatrix A addressing (unchanged from passing kernel)
    const int arow = (lane & 7) + (((lane >> 3) & 1) << 3);
    const unsigned int aoff = (unsigned)((arow * HS + ((lane >> 4) & 1) * 8) * 2);
    // ldmatrix B sub-offset within warp slab
    const int l2 = lane & 15;
    const unsigned int bsub = (unsigned)((l2 & 7) * WSTRB + ((l2 >> 3) & 1) * 16);
    // staging coords: lane -> (gate sg, row sr) of this warp's 32 slab rows
    const int sg = lane >> 3;         // 0..3
    const int sr = lane & 7;          // 0..7

    // stage chunk s of image into ring slot `slot` (warp-private, 1 group)
    auto stage = [&](const __half* img, int Kimg, int s, int slot) {
        unsigned int dst = wbase + (unsigned)(slot * SLABB + sg * GSTRB + sr * WSTRB);
        const __half* src = img + (sg * 128 + j0 + sr) * Kimg + s * 16;
        cp_async16(dst,      src);
        cp_async16(dst + 16, src + 8);
        cp_commit();
    };

    // ---- prologue: zero state, load biases/head ----
    for (int i = tid; i < ROWS * HS; i += THREADS) hcat[i] = __float2half(0.0f);
    for (int i = tid; i < ROWS * CS; i += THREADS) { cst0[i] = 0.0f; cst1[i] = 0.0f; }
    {
        int i = tid;  // THREADS == GATES
        bias[i]        = ebih0[i] + ebhh0[i];
        bias[512 + i]  = ebih1[i] + ebhh1[i];
        bias[1024 + i] = dbih0[i] + dbhh0[i];
        bias[1536 + i] = dbih1[i] + dbhh1[i];
    }
    if (tid < 256) headWs[tid] = headW[tid];
    if (tid < 2)   headbs[tid] = headb[tid];

    const __half* IMG_E0 = g_wimg + OFF_E0;
    const __half* IMG_E1 = g_wimg + OFF_E1;
    const __half* IMG_D0 = g_wimg + OFF_D0;
    const __half* IMG_D1 = g_wimg + OFF_D1;

    // pipeline prologue: chunks 0,1 of first matrix into slots 0,1
    stage(IMG_E0, K_L0, 0, 0);
    stage(IMG_E0, K_L0, 1, 1);
    int rslot = 0;
    __syncthreads();

    float acc[4][4][4];   // [mtile][gate][creg]

    auto init_acc = [&](const float* bs) {
        const int jc = j0 + 2 * tp;
#pragma unroll
        for (int g = 0; g < 4; ++g) {
            float b0 = bs[g * 128 + jc];
            float b1 = bs[g * 128 + jc + 1];
#pragma unroll
            for (int m = 0; m < 4; ++m) {
                acc[m][g][0] = b0; acc[m][g][1] = b1;
                acc[m][g][2] = b0; acc[m][g][3] = b1;
            }
        }
    };

    // barrier-free chunk loop: stage s+2 into (rslot+2)%3, wait own groups,
    // ldsm + 16 MMA. Ends with one __syncthreads (hcat reads drained).
    auto run_matrix = [&](const __half* img, int Kimg, int nk,
                          const __half* nimg, int nKimg) {
#pragma unroll 1
        for (int s = 0; s < nk; ++s) {
            int slot2 = rslot + 2; if (slot2 >= NRING) slot2 -= NRING;
            int t2 = s + 2;
            if (t2 < nk) stage(img,  Kimg,  t2,      slot2);
            else         stage(nimg, nKimg, t2 - nk, slot2);

            // A loads are independent of staging -> issue before the wait
            unsigned int a[4][4];
#pragma unroll
            for (int m = 0; m < 4; ++m)
                ldsm_x4(a[m], hcat_u32 + aoff + (unsigned)((m * 16 * HS + s * 16) * 2));

            cp_wait2();   // our chunk s slab has landed (committed 2 chunks ago)

            const unsigned int bb = wbase + (unsigned)(rslot * SLABB) + bsub;
            unsigned int b0[4], b1[4];
#pragma unroll
            for (int g = 0; g < 4; ++g)
                ldsm_x2(b0[g], b1[g], bb + (unsigned)(g * GSTRB));
#pragma unroll
            for (int g = 0; g < 4; ++g)
#pragma unroll
                for (int m = 0; m < 4; ++m)
                    mma16816(acc[m][g], a[m], b0[g], b1[g]);

            ++rslot; if (rslot == NRING) rslot = 0;
        }
        __syncthreads();   // all warps' hcat reads complete before overwrite
    };

    auto finish = [&](float* cs, int outcol) {
#pragma unroll
        for (int m = 0; m < 4; ++m) {
#pragma unroll
            for (int rr = 0; rr < 2; ++rr) {
                const int row = m * 16 + tg + rr * 8;
                const int jc  = j0 + 2 * tp;
                float hv[2];
#pragma unroll
                for (int cc = 0; cc < 2; ++cc) {
                    const int ci = rr * 2 + cc;
                    float gi = sigf(acc[m][0][ci]);
                    float gf = sigf(acc[m][1][ci]);
                    float gg = tanhf_fast(acc[m][2][ci]);
                    float go = sigf(acc[m][3][ci]);
                    float cold = cs[row * CS + jc + cc];
                    float cn = gf * cold + gi * gg;
                    cs[row * CS + jc + cc] = cn;
                    hv[cc] = go * tanhf_fast(cn);
                }
                *(__half2*)(hcat + row * HS + outcol + jc) =
                    __floats2half2_rn(hv[0], hv[1]);
            }
        }
        __syncthreads();   // new h visible to all warps before next matrix
    };

    // ================= encoder =================
#pragma unroll 1
    for (int t = 0; t < T_HIST; ++t) {
        // write x(t) into hcat cols 128..137; cols 138..143 stay 0
        for (int i = tid; i < ROWS * FIN; i += THREADS) {
            int r = i / FIN, f = i - r * FIN;
            hcat[r * HS + 128 + f] =
                __float2half(hist[(size_t)(brow + r) * (T_HIST * FIN) + t * FIN + f]);
        }
        __syncthreads();   // x visible before encL0 reads

        init_acc(bias);
        run_matrix(IMG_E0, K_L0, NK_L0, IMG_E1, K_L1);
        finish(cst0, 0);

        init_acc(bias + 512);
        run_matrix(IMG_E1, K_L1, NK_L1, (t + 1 < T_HIST) ? IMG_E0 : IMG_D0, K_L0);
        finish(cst1, 144);
    }

    // zero the x/y slot so decoder starts from y0 = 0
    for (int i = tid; i < ROWS * 16; i += THREADS) {
        int r = i >> 4, c = i & 15;
        hcat[r * HS + 128 + c] = __float2half(0.0f);
    }
    __syncthreads();

    // ================= decoder =================
#pragma unroll 1
    for (int t = 0; t < T_FUT; ++t) {
        init_acc(bias + 1024);
        run_matrix(IMG_D0, K_L0, NK_L0, IMG_D1, K_L1);
        finish(cst0, 0);

        init_acc(bias + 1536);
        run_matrix(IMG_D1, K_L1, NK_L1, IMG_D0, K_L0);
        finish(cst1, 144);

        // head: dxy = h1 @ headW^T + headb ; write y back into hcat fp16
        if (tid < ROWS * 2) {
            int r = tid >> 1, d = tid & 1;
            float s = headbs[d];
            const __half* hr = hcat + r * HS + 144;
            const float*  hw = headWs + d * 128;
#pragma unroll 8
            for (int jj = 0; jj < HID; ++jj)
                s += __half2float(hr[jj]) * hw[jj];
            out[(size_t)(brow + r) * (T_FUT * 2) + t * 2 + d] = s;
            hcat[r * HS + 128 + d] = __float2half(s);
        }
        __syncthreads();   // y visible before next decL0 reads
    }

    cp_wait0();   // drain dangling prefetch before CTA exit
}

extern "C" void kernel_launch(void* const* d_in, const int* in_sizes, int n_in,
                              void* d_out, int out_size)
{
    const float* hist  = (const float*)d_in[0];
    const float* eWih0 = (const float*)d_in[1];
    const float* eWhh0 = (const float*)d_in[2];
    const float* ebih0 = (const float*)d_in[3];
    const float* ebhh0 = (const float*)d_in[4];
    const float* eWih1 = (const float*)d_in[5];
    const float* eWhh1 = (const float*)d_in[6];
    const float* ebih1 = (const float*)d_in[7];
    const float* ebhh1 = (const float*)d_in[8];
    const float* dWih0 = (const float*)d_in[9];
    const float* dWhh0 = (const float*)d_in[10];
    const float* dbih0 = (const float*)d_in[11];
    const float* dbhh0 = (const float*)d_in[12];
    const float* dWih1 = (const float*)d_in[13];
    const float* dWhh1 = (const float*)d_in[14];
    const float* dbih1 = (const float*)d_in[15];
    const float* dbhh1 = (const float*)d_in[16];
    const float* headW = (const float*)d_in[17];
    const float* headb = (const float*)d_in[18];

    int B = in_sizes[0] / (T_HIST * FIN);
    int grid = B / ROWS;

    prep_weights<<<(WIMG_TOTAL + 511) / 512, 512>>>(
        eWih0, eWhh0, eWih1, eWhh1, dWih0, dWhh0, dWih1, dWhh1);

    cudaFuncSetAttribute(lstm_mma_kernel,
                         cudaFuncAttributeMaxDynamicSharedMemorySize, SMEM_BYTES);

    lstm_mma_kernel<<<grid, THREADS, SMEM_BYTES>>>(
        hist, ebih0, ebhh0, ebih1, ebhh1, dbih0, dbhh0, dbih1, dbhh1,
        headW, headb, (float*)d_out);
}